// round 6
// baseline (speedup 1.0000x reference)
#include <cuda_runtime.h>
#include <cuda_fp16.h>

#define NCH      256
#define NB       2
#define NBOX     512
#define K_ROIS   1024
#define OUT_PER_ROI 12544  // 256*49
// channels-last fp16 scratch: 27,200,000 halves = 54.4 MB (fits in L2)
__device__ __half g_cl[27200000];

// ---------------------------------------------------------------------------
// Pass A: fused transpose+downconvert [B,C,P]f32 -> [B,P,C]f16, all 4 levels.
// Tile = 32 pixels x 64 channels. smem is PIXEL-major fp16 (stride 66 halves).
// ---------------------------------------------------------------------------
__global__ __launch_bounds__(256) void transpose_all(const float* __restrict__ f0,
                                                     const float* __restrict__ f1,
                                                     const float* __restrict__ f2,
                                                     const float* __restrict__ f3)
{
    __shared__ __half tile[32 * 66];

    const int id = blockIdx.x;
    int lvl, rel;
    if      (id < 10000) { lvl = 0; rel = id;         }
    else if (id < 12504) { lvl = 1; rel = id - 10000; }
    else if (id < 13136) { lvl = 2; rel = id - 12504; }
    else                 { lvl = 3; rel = id - 13136; }

    const int P   = lvl == 0 ? 40000 : lvl == 1 ? 10000 : lvl == 2 ? 2500 : 625;
    const int pt  = lvl == 0 ? 1250  : lvl == 1 ? 313   : lvl == 2 ? 79   : 20;
    const int OFF = lvl == 0 ? 0 : lvl == 1 ? 20480000 : lvl == 2 ? 25600000 : 26880000;
    const float* __restrict__ src0 =
        lvl == 0 ? f0 : lvl == 1 ? f1 : lvl == 2 ? f2 : f3;

    const int ptile = rel % pt;
    const int rem   = rel / pt;
    const int c0    = (rem & 3) * 64;
    const int b     = rem >> 2;
    const int p0    = ptile * 32;

    const int tid = threadIdx.x;
    const int tx  = tid & 31;
    const int ty  = tid >> 5;

    const float* src = src0 + (size_t)b * NCH * P;
    const int p  = p0 + tx;
    const int pc = p < P ? p : P - 1;
    #pragma unroll
    for (int i = 0; i < 8; ++i) {
        const int cl = ty + i * 8;
        float v = src[(size_t)(c0 + cl) * P + pc];
        tile[tx * 66 + cl] = __float2half_rn(v);
    }
    __syncthreads();

    __half2* dst2 = (__half2*)(g_cl + OFF + (size_t)b * P * NCH);
    const __half2* t2 = (const __half2*)tile;
    const int c02 = (c0 >> 1);
    #pragma unroll
    for (int j = 0; j < 4; ++j) {
        const int pl = ty * 4 + j;
        const int pg = p0 + pl;
        if (pg < P)
            dst2[(size_t)pg * (NCH / 2) + c02 + tx] = t2[pl * 33 + tx];
    }
}

// ---------------------------------------------------------------------------
// Pass B: one block per ROI. 256 threads:
//   tid & 31 -> channel group (8 halves, one uint4), tid >> 5 -> bin group.
// Separable corner dedup: per bin-row, the 2 y-samples' 4 bilinear corners
// collapse to <=4 unique (row offset, weight) pairs; same per bin-col in x.
// Inner loop = my*mx deduped taps (warp-uniform counts).
// Shared layout (floats), base = 12544 (output stage [c][49]):
//   +0 rowcnt[7], +7 colcnt[7], +14 rowoff[28], +42 coloff[28],
//   +70 roww[28], +98 colw[28],
//   +126 ylsm[14], +140 xlsm[14], +154 lysm[14], +168 lxsm[14],
//   +182 vysm[14], +196 vxsm[14]   -> total 12754 floats
// ---------------------------------------------------------------------------
#define SMEM_FLOATS 12754
#define SMEM_BYTES  (SMEM_FLOATS * 4)

__global__ __launch_bounds__(256) void roi_kernel(const float* __restrict__ boxes,
                                                  float* __restrict__ out)
{
    extern __shared__ float smem[];
    float* stage  = smem;
    int*   rowcnt = (int*)(smem + 12544);
    int*   colcnt = rowcnt + 7;
    int*   rowoff = colcnt + 7;        // 28
    int*   coloff = rowoff + 28;       // 28
    float* roww   = (float*)(coloff + 28);  // 28
    float* colw   = roww + 28;              // 28
    int*   ylsm   = (int*)(colw + 28);      // 14
    int*   xlsm   = ylsm + 14;              // 14
    float* lysm   = (float*)(xlsm + 14);
    float* lxsm   = lysm + 14;
    float* vysm   = lxsm + 14;
    float* vxsm   = vysm + 14;

    const int k   = blockIdx.x;
    const int tid = threadIdx.x;
    const int b   = k >> 9;

    const float x1 = boxes[k * 4 + 0];
    const float y1 = boxes[k * 4 + 1];
    const float x2 = boxes[k * 4 + 2];
    const float y2 = boxes[k * 4 + 3];

    const float area = (x2 - x1) * (y2 - y1);
    const float sbox = sqrtf(fmaxf(area, 0.0f));
    const float lf   = floorf(4.0f + log2f(sbox / 224.0f) + 1e-6f);
    const int   lvl  = (int)fminf(fmaxf(lf, 2.0f), 5.0f) - 2;

    const int   H   = lvl == 0 ? 200 : lvl == 1 ? 100 : lvl == 2 ? 50 : 25;
    const float sc  = lvl == 0 ? 0.25f : lvl == 1 ? 0.125f : lvl == 2 ? 0.0625f : 0.03125f;
    const int   OFF = lvl == 0 ? 0 : lvl == 1 ? 20480000 : lvl == 2 ? 25600000 : 26880000;
    const int   W   = H;
    const int   rs  = W * NCH;

    const float bx1 = x1 * sc, by1 = y1 * sc;
    const float bx2 = x2 * sc, by2 = y2 * sc;
    const float rw  = fmaxf(bx2 - bx1, 1.0f);
    const float rh  = fmaxf(by2 - by1, 1.0f);
    const float bw  = rw * (1.0f / 7.0f);
    const float bh  = rh * (1.0f / 7.0f);

    // --- phase 1: separable y / x sample precompute (14 samples each) ---
    if (tid < 14) {
        const int iy = tid;
        const float y = by1 + (float)(iy >> 1) * bh + ((float)(iy & 1) + 0.5f) * bh * 0.5f;
        const float v = (y >= -1.0f && y <= (float)H) ? 1.0f : 0.0f;
        const float yc = fminf(fmaxf(y, 0.0f), (float)(H - 1));
        int yl = (int)floorf(yc);
        if (yl > H - 2) yl = H - 2;
        ylsm[iy] = yl;
        lysm[iy] = yc - (float)yl;
        vysm[iy] = v;
    } else if (tid >= 32 && tid < 46) {
        const int ix = tid - 32;
        const float x = bx1 + (float)(ix >> 1) * bw + ((float)(ix & 1) + 0.5f) * bw * 0.5f;
        const float v = (x >= -1.0f && x <= (float)W) ? 1.0f : 0.0f;
        const float xc = fminf(fmaxf(x, 0.0f), (float)(W - 1));
        int xl = (int)floorf(xc);
        if (xl > W - 2) xl = W - 2;
        xlsm[ix] = xl;
        lxsm[ix] = xc - (float)xl;
        vxsm[ix] = v;
    }
    __syncthreads();

    // --- phase 2: per-bin corner dedup (y rows: tid<7, x cols: tid in [32,39)) ---
    if (tid < 7) {
        const int ph = tid, base = ph * 4;
        int cnt = 0;
        #pragma unroll
        for (int s = 0; s < 2; ++s) {
            const int iy = ph * 2 + s;
            const float vy = vysm[iy] * 0.5f;   // fold 1/2 of the 1/4 sample mean
            const float ly = lysm[iy];
            const int   o0 = ylsm[iy] * rs;
            const float wA = (1.0f - ly) * vy;
            const float wB = ly * vy;
            #pragma unroll
            for (int e = 0; e < 2; ++e) {
                const int   o = e ? o0 + rs : o0;
                const float w = e ? wB : wA;
                if (w != 0.0f) {
                    int f = -1;
                    for (int t = 0; t < cnt; ++t)
                        if (rowoff[base + t] == o) f = t;
                    if (f >= 0) roww[base + f] += w;
                    else { rowoff[base + cnt] = o; roww[base + cnt] = w; ++cnt; }
                }
            }
        }
        rowcnt[ph] = cnt;
    } else if (tid >= 32 && tid < 39) {
        const int pw = tid - 32, base = pw * 4;
        int cnt = 0;
        #pragma unroll
        for (int s = 0; s < 2; ++s) {
            const int ix = pw * 2 + s;
            const float vx = vxsm[ix] * 0.5f;
            const float lx = lxsm[ix];
            const int   o0 = xlsm[ix] * NCH;
            const float wA = (1.0f - lx) * vx;
            const float wB = lx * vx;
            #pragma unroll
            for (int e = 0; e < 2; ++e) {
                const int   o = e ? o0 + NCH : o0;
                const float w = e ? wB : wA;
                if (w != 0.0f) {
                    int f = -1;
                    for (int t = 0; t < cnt; ++t)
                        if (coloff[base + t] == o) f = t;
                    if (f >= 0) colw[base + f] += w;
                    else { coloff[base + cnt] = o; colw[base + cnt] = w; ++cnt; }
                }
            }
        }
        colcnt[pw] = cnt;
    }
    __syncthreads();

    // --- phase 3: deduped taps; warp-uniform my*mx loop per bin ---
    const int cg = tid & 31;
    const int bg = tid >> 5;
    const __half* fb = g_cl + OFF + (size_t)b * H * W * NCH + cg * 8;

    for (int bin = bg; bin < 49; bin += 8) {
        const int ph = bin / 7;
        const int pw = bin - ph * 7;
        const int my = rowcnt[ph];
        const int mx = colcnt[pw];
        float a0 = 0.f, a1 = 0.f, a2 = 0.f, a3 = 0.f;
        float a4 = 0.f, a5 = 0.f, a6 = 0.f, a7 = 0.f;
        for (int i = 0; i < my; ++i) {
            const __half* rp = fb + rowoff[ph * 4 + i];
            const float  wr = roww[ph * 4 + i];
            #pragma unroll 4
            for (int j = 0; j < mx; ++j) {
                const float w = wr * colw[pw * 4 + j];
                const uint4 r = *(const uint4*)(rp + coloff[pw * 4 + j]);
                const float2 v0 = __half22float2(((const __half2*)&r)[0]);
                const float2 v1 = __half22float2(((const __half2*)&r)[1]);
                const float2 v2 = __half22float2(((const __half2*)&r)[2]);
                const float2 v3 = __half22float2(((const __half2*)&r)[3]);
                a0 += w * v0.x;  a1 += w * v0.y;
                a2 += w * v1.x;  a3 += w * v1.y;
                a4 += w * v2.x;  a5 += w * v2.y;
                a6 += w * v3.x;  a7 += w * v3.y;
            }
        }
        const int base = (cg * 8) * 49 + bin;
        stage[base         ] = a0;
        stage[base + 49    ] = a1;
        stage[base + 49 * 2] = a2;
        stage[base + 49 * 3] = a3;
        stage[base + 49 * 4] = a4;
        stage[base + 49 * 5] = a5;
        stage[base + 49 * 6] = a6;
        stage[base + 49 * 7] = a7;
    }
    __syncthreads();

    // --- phase 4: fully coalesced float4 writeback of the ROI tile ---
    float4* op = (float4*)(out + (size_t)k * OUT_PER_ROI);
    const float4* sp = (const float4*)stage;
    for (int v = tid; v < OUT_PER_ROI / 4; v += 256)
        op[v] = sp[v];
}

// ---------------------------------------------------------------------------
extern "C" void kernel_launch(void* const* d_in, const int* in_sizes, int n_in,
                              void* d_out, int out_size)
{
    (void)in_sizes; (void)n_in; (void)out_size;
    const float* boxes = (const float*)d_in[4];
    float* out = (float*)d_out;

    cudaFuncSetAttribute(roi_kernel,
                         cudaFuncAttributeMaxDynamicSharedMemorySize, SMEM_BYTES);

    transpose_all<<<13296, 256>>>((const float*)d_in[0], (const float*)d_in[1],
                                  (const float*)d_in[2], (const float*)d_in[3]);

    roi_kernel<<<K_ROIS, 256, SMEM_BYTES>>>(boxes, out);
}

// round 10
// speedup vs baseline: 1.4053x; 1.4053x over previous
#include <cuda_runtime.h>
#include <cuda_fp16.h>

#define NCH      256
#define NB       2
#define NBOX     512
#define K_ROIS   1024
#define NSAMP    14
#define OUT_PER_ROI 12544  // 256*49
// channels-last fp16 scratch: 27,200,000 halves = 54.4 MB (fits in L2)
__device__ __half g_cl[27200000];

// ---------------------------------------------------------------------------
// Pass A: fused transpose+downconvert [B,C,P]f32 -> [B,P,C]f16, all 4 levels.
// Tile = 32 pixels x 64 channels. smem is PIXEL-major fp16 (stride 66 halves).
// ---------------------------------------------------------------------------
__global__ __launch_bounds__(256) void transpose_all(const float* __restrict__ f0,
                                                     const float* __restrict__ f1,
                                                     const float* __restrict__ f2,
                                                     const float* __restrict__ f3)
{
    __shared__ __half tile[32 * 66];

    const int id = blockIdx.x;
    int lvl, rel;
    if      (id < 10000) { lvl = 0; rel = id;         }
    else if (id < 12504) { lvl = 1; rel = id - 10000; }
    else if (id < 13136) { lvl = 2; rel = id - 12504; }
    else                 { lvl = 3; rel = id - 13136; }

    const int P   = lvl == 0 ? 40000 : lvl == 1 ? 10000 : lvl == 2 ? 2500 : 625;
    const int pt  = lvl == 0 ? 1250  : lvl == 1 ? 313   : lvl == 2 ? 79   : 20;
    const int OFF = lvl == 0 ? 0 : lvl == 1 ? 20480000 : lvl == 2 ? 25600000 : 26880000;
    const float* __restrict__ src0 =
        lvl == 0 ? f0 : lvl == 1 ? f1 : lvl == 2 ? f2 : f3;

    const int ptile = rel % pt;
    const int rem   = rel / pt;
    const int c0    = (rem & 3) * 64;
    const int b     = rem >> 2;
    const int p0    = ptile * 32;

    const int tid = threadIdx.x;
    const int tx  = tid & 31;
    const int ty  = tid >> 5;

    const float* src = src0 + (size_t)b * NCH * P;
    const int p  = p0 + tx;
    const int pc = p < P ? p : P - 1;
    #pragma unroll
    for (int i = 0; i < 8; ++i) {
        const int cl = ty + i * 8;
        float v = src[(size_t)(c0 + cl) * P + pc];
        tile[tx * 66 + cl] = __float2half_rn(v);
    }
    __syncthreads();

    __half2* dst2 = (__half2*)(g_cl + OFF + (size_t)b * P * NCH);
    const __half2* t2 = (const __half2*)tile;
    const int c02 = (c0 >> 1);
    #pragma unroll
    for (int j = 0; j < 4; ++j) {
        const int pl = ty * 4 + j;
        const int pg = p0 + pl;
        if (pg < P)
            dst2[(size_t)pg * (NCH / 2) + c02 + tx] = t2[pl * 33 + tx];
    }
}

// ---------------------------------------------------------------------------
// Pass B: one block per ROI. 256 threads:
//   tid & 31 -> channel group (8 halves, one uint4), tid >> 5 -> bin group.
// Static 16-tap inner loop (max MLP). fp16 output staging (25KB smem) +
// launch_bounds(256,5) -> 5 blocks/SM (62.5% occ).
// smem layout (bytes):
//   [0, 25088)            stage: 12544 halves, [c][49]
//   [25088, 28224)        wsm:   196 float4
//   [28224, 29008)        offsm: 196 int
//   [29008, 29344)        y/x precompute: 2x14 int + 4x14 float
// ---------------------------------------------------------------------------
#define SMEM_BYTES 29344

__global__ __launch_bounds__(256, 5) void roi_kernel(const float* __restrict__ boxes,
                                                     float* __restrict__ out)
{
    extern __shared__ char smraw[];
    __half* stage = (__half*)smraw;                 // 12544 halves
    float4* wsm   = (float4*)(smraw + 25088);       // 196
    int*    offsm = (int*)(smraw + 28224);          // 196
    int*    ylsm  = offsm + 196;                    // 14
    int*    xlsm  = ylsm + 14;                      // 14
    float*  lysm  = (float*)(xlsm + 14);            // 14
    float*  lxsm  = lysm + 14;                      // 14
    float*  vysm  = lxsm + 14;                      // 14
    float*  vxsm  = vysm + 14;                      // 14

    const int k   = blockIdx.x;
    const int tid = threadIdx.x;
    const int b   = k >> 9;

    const float x1 = boxes[k * 4 + 0];
    const float y1 = boxes[k * 4 + 1];
    const float x2 = boxes[k * 4 + 2];
    const float y2 = boxes[k * 4 + 3];

    const float area = (x2 - x1) * (y2 - y1);
    const float sbox = sqrtf(fmaxf(area, 0.0f));
    const float lf   = floorf(4.0f + log2f(sbox / 224.0f) + 1e-6f);
    const int   lvl  = (int)fminf(fmaxf(lf, 2.0f), 5.0f) - 2;

    const int   H   = lvl == 0 ? 200 : lvl == 1 ? 100 : lvl == 2 ? 50 : 25;
    const float sc  = lvl == 0 ? 0.25f : lvl == 1 ? 0.125f : lvl == 2 ? 0.0625f : 0.03125f;
    const int   OFF = lvl == 0 ? 0 : lvl == 1 ? 20480000 : lvl == 2 ? 25600000 : 26880000;
    const int   W   = H;

    const float bx1 = x1 * sc, by1 = y1 * sc;
    const float bx2 = x2 * sc, by2 = y2 * sc;
    const float rw  = fmaxf(bx2 - bx1, 1.0f);
    const float rh  = fmaxf(by2 - by1, 1.0f);
    const float bw  = rw * (1.0f / 7.0f);
    const float bh  = rh * (1.0f / 7.0f);

    // --- phase 1: separable y / x sample precompute ---
    if (tid < 14) {
        const int iy = tid;
        const float y = by1 + (float)(iy >> 1) * bh + ((float)(iy & 1) + 0.5f) * bh * 0.5f;
        const float v = (y >= -1.0f && y <= (float)H) ? 1.0f : 0.0f;
        const float yc = fminf(fmaxf(y, 0.0f), (float)(H - 1));
        int yl = (int)floorf(yc);
        if (yl > H - 2) yl = H - 2;
        ylsm[iy] = yl;
        lysm[iy] = yc - (float)yl;
        vysm[iy] = v;
    } else if (tid >= 32 && tid < 46) {
        const int ix = tid - 32;
        const float x = bx1 + (float)(ix >> 1) * bw + ((float)(ix & 1) + 0.5f) * bw * 0.5f;
        const float v = (x >= -1.0f && x <= (float)W) ? 1.0f : 0.0f;
        const float xc = fminf(fmaxf(x, 0.0f), (float)(W - 1));
        int xl = (int)floorf(xc);
        if (xl > W - 2) xl = W - 2;
        xlsm[ix] = xl;
        lxsm[ix] = xc - (float)xl;
        vxsm[ix] = v;
    }
    __syncthreads();

    // --- phase 2: per-sample combined offset + 4 bilinear weights ---
    for (int ss = tid; ss < NSAMP * NSAMP; ss += 256) {
        const int iy = ss / NSAMP;
        const int ix = ss - iy * NSAMP;
        const float ly = lysm[iy], lx = lxsm[ix];
        const float v  = vysm[iy] * vxsm[ix];
        const float hy = 1.0f - ly, hx = 1.0f - lx;
        wsm[ss]   = make_float4(hy * hx * v, hy * lx * v, ly * hx * v, ly * lx * v);
        offsm[ss] = (ylsm[iy] * W + xlsm[ix]) * NCH;   // in halves (elements)
    }
    __syncthreads();

    // --- phase 3: 49 bins over 8 bin-groups; static 16 taps per bin ---
    const int cg = tid & 31;
    const int bg = tid >> 5;
    const __half* fb = g_cl + OFF + (size_t)b * H * W * NCH + cg * 8;
    const int rs = W * NCH;   // +1 feature row, in halves

    for (int bin = bg; bin < 49; bin += 8) {
        const int ph = bin / 7;
        const int pw = bin - ph * 7;
        float a0 = 0.f, a1 = 0.f, a2 = 0.f, a3 = 0.f;
        float a4 = 0.f, a5 = 0.f, a6 = 0.f, a7 = 0.f;
        #pragma unroll
        for (int sub = 0; sub < 4; ++sub) {
            const int sI = (ph * 2 + (sub >> 1)) * NSAMP + (pw * 2 + (sub & 1));
            const float4 w = wsm[sI];
            const int    o = offsm[sI];
            const uint4 r00 = *(const uint4*)(fb + o);
            const uint4 r01 = *(const uint4*)(fb + o + NCH);
            const uint4 r10 = *(const uint4*)(fb + o + rs);
            const uint4 r11 = *(const uint4*)(fb + o + rs + NCH);
            #pragma unroll
            for (int j = 0; j < 4; ++j) {
                const float2 v00 = __half22float2(((const __half2*)&r00)[j]);
                const float2 v01 = __half22float2(((const __half2*)&r01)[j]);
                const float2 v10 = __half22float2(((const __half2*)&r10)[j]);
                const float2 v11 = __half22float2(((const __half2*)&r11)[j]);
                float lo = w.x * v00.x + w.y * v01.x + w.z * v10.x + w.w * v11.x;
                float hi = w.x * v00.y + w.y * v01.y + w.z * v10.y + w.w * v11.y;
                switch (j) {
                    case 0: a0 += lo; a1 += hi; break;
                    case 1: a2 += lo; a3 += hi; break;
                    case 2: a4 += lo; a5 += hi; break;
                    case 3: a6 += lo; a7 += hi; break;
                }
            }
        }
        const int base = (cg * 8) * 49 + bin;
        stage[base          ] = __float2half_rn(a0 * 0.25f);
        stage[base +  49    ] = __float2half_rn(a1 * 0.25f);
        stage[base +  49 * 2] = __float2half_rn(a2 * 0.25f);
        stage[base +  49 * 3] = __float2half_rn(a3 * 0.25f);
        stage[base +  49 * 4] = __float2half_rn(a4 * 0.25f);
        stage[base +  49 * 5] = __float2half_rn(a5 * 0.25f);
        stage[base +  49 * 6] = __float2half_rn(a6 * 0.25f);
        stage[base +  49 * 7] = __float2half_rn(a7 * 0.25f);
    }
    __syncthreads();

    // --- phase 4: coalesced writeback, fp16 stage -> f32 out (float4) ---
    float4* op = (float4*)(out + (size_t)k * OUT_PER_ROI);
    const uint2* sp = (const uint2*)stage;          // 3136 uint2 = 12544 halves
    for (int v = tid; v < OUT_PER_ROI / 4; v += 256) {
        const uint2 r = sp[v];
        const float2 f0 = __half22float2(*(const __half2*)&r.x);
        const float2 f1 = __half22float2(*(const __half2*)&r.y);
        op[v] = make_float4(f0.x, f0.y, f1.x, f1.y);
    }
}

// ---------------------------------------------------------------------------
extern "C" void kernel_launch(void* const* d_in, const int* in_sizes, int n_in,
                              void* d_out, int out_size)
{
    (void)in_sizes; (void)n_in; (void)out_size;
    const float* boxes = (const float*)d_in[4];
    float* out = (float*)d_out;

    transpose_all<<<13296, 256>>>((const float*)d_in[0], (const float*)d_in[1],
                                  (const float*)d_in[2], (const float*)d_in[3]);

    roi_kernel<<<K_ROIS, 256, SMEM_BYTES>>>(boxes, out);
}

// round 11
// speedup vs baseline: 1.5686x; 1.1162x over previous
#include <cuda_runtime.h>
#include <cuda_fp16.h>

#define NCH      256
#define NB       2
#define NBOX     512
#define K_ROIS   1024
#define NSAMP    14
#define OUT_PER_ROI 12544  // 256*49
// channels-last fp16 scratch: 27,200,000 halves = 54.4 MB
__device__ __half g_cl[27200000];

// ---------------------------------------------------------------------------
// Pass A: fused transpose+downconvert [B,C,P]f32 -> [B,P,C]f16, all 4 levels.
// Tile = 64 pixels x 64 channels, float2 reads (256B per warp-row).
// Block counts (pt * 4 ctiles * 2 b): L0 5000, L1 1256, L2 320, L3 80 -> 6656.
// ---------------------------------------------------------------------------
__global__ __launch_bounds__(256) void transpose_all(const float* __restrict__ f0,
                                                     const float* __restrict__ f1,
                                                     const float* __restrict__ f2,
                                                     const float* __restrict__ f3)
{
    __shared__ __half tile[64 * 66];   // [pixel][channel], pad 2

    const int id = blockIdx.x;
    int lvl, rel;
    if      (id < 5000) { lvl = 0; rel = id;        }
    else if (id < 6256) { lvl = 1; rel = id - 5000; }
    else if (id < 6576) { lvl = 2; rel = id - 6256; }
    else                { lvl = 3; rel = id - 6576; }

    const int P   = lvl == 0 ? 40000 : lvl == 1 ? 10000 : lvl == 2 ? 2500 : 625;
    const int pt  = lvl == 0 ? 625   : lvl == 1 ? 157   : lvl == 2 ? 40   : 10;
    const int OFF = lvl == 0 ? 0 : lvl == 1 ? 20480000 : lvl == 2 ? 25600000 : 26880000;
    const float* __restrict__ src0 =
        lvl == 0 ? f0 : lvl == 1 ? f1 : lvl == 2 ? f2 : f3;

    const int ptile = rel % pt;
    const int rem   = rel / pt;
    const int c0    = (rem & 3) * 64;
    const int b     = rem >> 2;
    const int p0    = ptile * 64;

    const int tid = threadIdx.x;
    const int tx  = tid & 31;    // pixel-pair index
    const int ty  = tid >> 5;    // 0..7

    const float* src = src0 + (size_t)b * NCH * P;
    const int p = p0 + 2 * tx;

    if (!(P & 1)) {
        // P even, p even: pa+1 <= P-1 always safe; OOB-tile values never written
        const int pa = p < P ? p : P - 2;
        #pragma unroll
        for (int i = 0; i < 8; ++i) {
            const int cl = ty + i * 8;
            const float2 v = *(const float2*)(src + (size_t)(c0 + cl) * P + pa);
            tile[(2 * tx)     * 66 + cl] = __float2half_rn(v.x);
            tile[(2 * tx + 1) * 66 + cl] = __float2half_rn(v.y);
        }
    } else {
        // odd-stride level (P=625): scalar clamped loads
        const int pa = p     < P ? p     : P - 1;
        const int pb = p + 1 < P ? p + 1 : P - 1;
        #pragma unroll
        for (int i = 0; i < 8; ++i) {
            const int cl = ty + i * 8;
            tile[(2 * tx)     * 66 + cl] = __float2half_rn(src[(size_t)(c0 + cl) * P + pa]);
            tile[(2 * tx + 1) * 66 + cl] = __float2half_rn(src[(size_t)(c0 + cl) * P + pb]);
        }
    }
    __syncthreads();

    // write: warp emits one pixel's 64 ch = 32 half2 = 128B contiguous per iter
    __half2* dst2 = (__half2*)(g_cl + OFF + (size_t)b * P * NCH);
    const __half2* t2 = (const __half2*)tile;
    const int c02 = (c0 >> 1);
    #pragma unroll
    for (int j = 0; j < 8; ++j) {
        const int pl = ty * 8 + j;
        const int pg = p0 + pl;
        if (pg < P)
            dst2[(size_t)pg * (NCH / 2) + c02 + tx] = t2[pl * 33 + tx];
    }
}

// ---------------------------------------------------------------------------
// Pass B: 2 blocks per ROI (2048 blocks, better wave balance). 256 threads:
//   tid & 15 -> channel group (8 halves, one uint4) within this half's 128 ch
//   tid >> 4 -> bin group (16 groups over 49 bins)
// Static 16-tap inner loop. fp16 staging (12.5KB). smem total 16.8KB.
// smem layout (bytes):
//   [0, 12544)        stage: 6272 halves, [lc][49]
//   [12544, 15680)    wsm:   196 float4 (0.25 pre-folded)
//   [15680, 16464)    offsm: 196 int
//   [16464, 16800)    y/x precompute: 2x14 int + 4x14 float
// ---------------------------------------------------------------------------
#define SMEM_BYTES 16800

__global__ __launch_bounds__(256, 5) void roi_kernel(const float* __restrict__ boxes,
                                                     float* __restrict__ out)
{
    extern __shared__ char smraw[];
    __half* stage = (__half*)smraw;                 // 6272 halves
    float4* wsm   = (float4*)(smraw + 12544);       // 196
    int*    offsm = (int*)(smraw + 15680);          // 196
    int*    ylsm  = offsm + 196;                    // 14
    int*    xlsm  = ylsm + 14;                      // 14
    float*  lysm  = (float*)(xlsm + 14);            // 14
    float*  lxsm  = lysm + 14;                      // 14
    float*  vysm  = lxsm + 14;                      // 14
    float*  vxsm  = vysm + 14;                      // 14

    const int bid = blockIdx.x;
    const int k   = bid >> 1;          // ROI
    const int h   = bid & 1;           // channel half: [h*128, h*128+128)
    const int tid = threadIdx.x;
    const int b   = k >> 9;

    const float x1 = boxes[k * 4 + 0];
    const float y1 = boxes[k * 4 + 1];
    const float x2 = boxes[k * 4 + 2];
    const float y2 = boxes[k * 4 + 3];

    const float area = (x2 - x1) * (y2 - y1);
    const float sbox = sqrtf(fmaxf(area, 0.0f));
    const float lf   = floorf(4.0f + log2f(sbox / 224.0f) + 1e-6f);
    const int   lvl  = (int)fminf(fmaxf(lf, 2.0f), 5.0f) - 2;

    const int   H   = lvl == 0 ? 200 : lvl == 1 ? 100 : lvl == 2 ? 50 : 25;
    const float sc  = lvl == 0 ? 0.25f : lvl == 1 ? 0.125f : lvl == 2 ? 0.0625f : 0.03125f;
    const int   OFF = lvl == 0 ? 0 : lvl == 1 ? 20480000 : lvl == 2 ? 25600000 : 26880000;
    const int   W   = H;

    const float bx1 = x1 * sc, by1 = y1 * sc;
    const float bx2 = x2 * sc, by2 = y2 * sc;
    const float rw  = fmaxf(bx2 - bx1, 1.0f);
    const float rh  = fmaxf(by2 - by1, 1.0f);
    const float bw  = rw * (1.0f / 7.0f);
    const float bh  = rh * (1.0f / 7.0f);

    // --- phase 1: separable y / x sample precompute ---
    if (tid < 14) {
        const int iy = tid;
        const float y = by1 + (float)(iy >> 1) * bh + ((float)(iy & 1) + 0.5f) * bh * 0.5f;
        const float v = (y >= -1.0f && y <= (float)H) ? 1.0f : 0.0f;
        const float yc = fminf(fmaxf(y, 0.0f), (float)(H - 1));
        int yl = (int)floorf(yc);
        if (yl > H - 2) yl = H - 2;
        ylsm[iy] = yl;
        lysm[iy] = yc - (float)yl;
        vysm[iy] = v;
    } else if (tid >= 32 && tid < 46) {
        const int ix = tid - 32;
        const float x = bx1 + (float)(ix >> 1) * bw + ((float)(ix & 1) + 0.5f) * bw * 0.5f;
        const float v = (x >= -1.0f && x <= (float)W) ? 1.0f : 0.0f;
        const float xc = fminf(fmaxf(x, 0.0f), (float)(W - 1));
        int xl = (int)floorf(xc);
        if (xl > W - 2) xl = W - 2;
        xlsm[ix] = xl;
        lxsm[ix] = xc - (float)xl;
        vxsm[ix] = v;
    }
    __syncthreads();

    // --- phase 2: per-sample offset + 4 bilinear weights (0.25 folded in) ---
    for (int ss = tid; ss < NSAMP * NSAMP; ss += 256) {
        const int iy = ss / NSAMP;
        const int ix = ss - iy * NSAMP;
        const float ly = lysm[iy], lx = lxsm[ix];
        const float v  = vysm[iy] * vxsm[ix] * 0.25f;
        const float hy = 1.0f - ly, hx = 1.0f - lx;
        wsm[ss]   = make_float4(hy * hx * v, hy * lx * v, ly * hx * v, ly * lx * v);
        offsm[ss] = (ylsm[iy] * W + xlsm[ix]) * NCH;   // in halves
    }
    __syncthreads();

    // --- phase 3: 49 bins over 16 bin-groups; static 16 taps per bin ---
    const int cg = tid & 15;
    const int bg = tid >> 4;
    const __half* fb = g_cl + OFF + (size_t)b * H * W * NCH + h * 128 + cg * 8;
    const int rs = W * NCH;   // +1 feature row, in halves

    for (int bin = bg; bin < 49; bin += 16) {
        const int ph = bin / 7;
        const int pw = bin - ph * 7;
        float a0 = 0.f, a1 = 0.f, a2 = 0.f, a3 = 0.f;
        float a4 = 0.f, a5 = 0.f, a6 = 0.f, a7 = 0.f;
        #pragma unroll
        for (int sub = 0; sub < 4; ++sub) {
            const int sI = (ph * 2 + (sub >> 1)) * NSAMP + (pw * 2 + (sub & 1));
            const float4 w = wsm[sI];
            const int    o = offsm[sI];
            const uint4 r00 = *(const uint4*)(fb + o);
            const uint4 r01 = *(const uint4*)(fb + o + NCH);
            const uint4 r10 = *(const uint4*)(fb + o + rs);
            const uint4 r11 = *(const uint4*)(fb + o + rs + NCH);
            #pragma unroll
            for (int j = 0; j < 4; ++j) {
                const float2 v00 = __half22float2(((const __half2*)&r00)[j]);
                const float2 v01 = __half22float2(((const __half2*)&r01)[j]);
                const float2 v10 = __half22float2(((const __half2*)&r10)[j]);
                const float2 v11 = __half22float2(((const __half2*)&r11)[j]);
                float lo = w.x * v00.x + w.y * v01.x + w.z * v10.x + w.w * v11.x;
                float hi = w.x * v00.y + w.y * v01.y + w.z * v10.y + w.w * v11.y;
                switch (j) {
                    case 0: a0 += lo; a1 += hi; break;
                    case 1: a2 += lo; a3 += hi; break;
                    case 2: a4 += lo; a5 += hi; break;
                    case 3: a6 += lo; a7 += hi; break;
                }
            }
        }
        const int base = (cg * 8) * 49 + bin;   // local channel lc = cg*8
        stage[base          ] = __float2half_rn(a0);
        stage[base +  49    ] = __float2half_rn(a1);
        stage[base +  49 * 2] = __float2half_rn(a2);
        stage[base +  49 * 3] = __float2half_rn(a3);
        stage[base +  49 * 4] = __float2half_rn(a4);
        stage[base +  49 * 5] = __float2half_rn(a5);
        stage[base +  49 * 6] = __float2half_rn(a6);
        stage[base +  49 * 7] = __float2half_rn(a7);
    }
    __syncthreads();

    // --- phase 4: coalesced writeback, fp16 stage -> f32 out (float4) ---
    float4* op = (float4*)(out + (size_t)k * OUT_PER_ROI + h * 6272);
    const uint2* sp = (const uint2*)stage;          // 1568 uint2 = 6272 halves
    for (int v = tid; v < 6272 / 4; v += 256) {
        const uint2 r = sp[v];
        const float2 g0 = __half22float2(*(const __half2*)&r.x);
        const float2 g1 = __half22float2(*(const __half2*)&r.y);
        op[v] = make_float4(g0.x, g0.y, g1.x, g1.y);
    }
}

// ---------------------------------------------------------------------------
extern "C" void kernel_launch(void* const* d_in, const int* in_sizes, int n_in,
                              void* d_out, int out_size)
{
    (void)in_sizes; (void)n_in; (void)out_size;
    const float* boxes = (const float*)d_in[4];
    float* out = (float*)d_out;

    transpose_all<<<6656, 256>>>((const float*)d_in[0], (const float*)d_in[1],
                                 (const float*)d_in[2], (const float*)d_in[3]);

    roi_kernel<<<2 * K_ROIS, 256, SMEM_BYTES>>>(boxes, out);
}

// round 12
// speedup vs baseline: 1.6398x; 1.0454x over previous
#include <cuda_runtime.h>
#include <cuda_fp16.h>

#define NCH      256
#define NB       2
#define NBOX     512
#define K_ROIS   1024
#define NSAMP    14
#define OUT_PER_ROI 12544  // 256*49
// channels-last fp16 scratch: 27,200,000 halves = 54.4 MB
__device__ __half g_cl[27200000];

static __device__ __forceinline__ unsigned h2u(__half2 h) {
    return *reinterpret_cast<unsigned*>(&h);
}

// ---------------------------------------------------------------------------
// Pass A: fused transpose+downconvert [B,C,P]f32 -> [B,P,C]f16, all 4 levels.
// Tile = 64 pixels x 64 channels, float2 reads (256B per warp-row).
// ---------------------------------------------------------------------------
__global__ __launch_bounds__(256) void transpose_all(const float* __restrict__ f0,
                                                     const float* __restrict__ f1,
                                                     const float* __restrict__ f2,
                                                     const float* __restrict__ f3)
{
    __shared__ __half tile[64 * 66];

    const int id = blockIdx.x;
    int lvl, rel;
    if      (id < 5000) { lvl = 0; rel = id;        }
    else if (id < 6256) { lvl = 1; rel = id - 5000; }
    else if (id < 6576) { lvl = 2; rel = id - 6256; }
    else                { lvl = 3; rel = id - 6576; }

    const int P   = lvl == 0 ? 40000 : lvl == 1 ? 10000 : lvl == 2 ? 2500 : 625;
    const int pt  = lvl == 0 ? 625   : lvl == 1 ? 157   : lvl == 2 ? 40   : 10;
    const int OFF = lvl == 0 ? 0 : lvl == 1 ? 20480000 : lvl == 2 ? 25600000 : 26880000;
    const float* __restrict__ src0 =
        lvl == 0 ? f0 : lvl == 1 ? f1 : lvl == 2 ? f2 : f3;

    const int ptile = rel % pt;
    const int rem   = rel / pt;
    const int c0    = (rem & 3) * 64;
    const int b     = rem >> 2;
    const int p0    = ptile * 64;

    const int tid = threadIdx.x;
    const int tx  = tid & 31;
    const int ty  = tid >> 5;

    const float* src = src0 + (size_t)b * NCH * P;
    const int p = p0 + 2 * tx;

    if (!(P & 1)) {
        const int pa = p < P ? p : P - 2;
        #pragma unroll
        for (int i = 0; i < 8; ++i) {
            const int cl = ty + i * 8;
            const float2 v = *(const float2*)(src + (size_t)(c0 + cl) * P + pa);
            tile[(2 * tx)     * 66 + cl] = __float2half_rn(v.x);
            tile[(2 * tx + 1) * 66 + cl] = __float2half_rn(v.y);
        }
    } else {
        const int pa = p     < P ? p     : P - 1;
        const int pb = p + 1 < P ? p + 1 : P - 1;
        #pragma unroll
        for (int i = 0; i < 8; ++i) {
            const int cl = ty + i * 8;
            tile[(2 * tx)     * 66 + cl] = __float2half_rn(src[(size_t)(c0 + cl) * P + pa]);
            tile[(2 * tx + 1) * 66 + cl] = __float2half_rn(src[(size_t)(c0 + cl) * P + pb]);
        }
    }
    __syncthreads();

    __half2* dst2 = (__half2*)(g_cl + OFF + (size_t)b * P * NCH);
    const __half2* t2 = (const __half2*)tile;
    const int c02 = (c0 >> 1);
    #pragma unroll
    for (int j = 0; j < 8; ++j) {
        const int pl = ty * 8 + j;
        const int pg = p0 + pl;
        if (pg < P)
            dst2[(size_t)pg * (NCH / 2) + c02 + tx] = t2[pl * 33 + tx];
    }
}

// ---------------------------------------------------------------------------
// Pass B: 2 blocks per ROI (2048 blocks). 256 threads:
//   tid & 15 -> channel group (8 halves, one uint4), tid >> 4 -> bin group.
// HFMA2 inner arithmetic: per sub-sample, 2-deep fp16 chains, fp32 cross-sub
// accumulation. Weights stored as packed broadcast half2 quads (uint4).
// smem layout (bytes):
//   [0, 12544)        stage: 6272 halves, [lc][49]
//   [12544, 15680)    whsm:  196 uint4 (4 broadcast half2 weights, 0.25 folded)
//   [15680, 16464)    offsm: 196 int
//   [16464, 16800)    y/x precompute
// ---------------------------------------------------------------------------
#define SMEM_BYTES 16800

__global__ __launch_bounds__(256, 5) void roi_kernel(const float* __restrict__ boxes,
                                                     float* __restrict__ out)
{
    extern __shared__ char smraw[];
    __half* stage = (__half*)smraw;                 // 6272 halves
    uint4*  whsm  = (uint4*)(smraw + 12544);        // 196
    int*    offsm = (int*)(smraw + 15680);          // 196
    int*    ylsm  = offsm + 196;                    // 14
    int*    xlsm  = ylsm + 14;                      // 14
    float*  lysm  = (float*)(xlsm + 14);            // 14
    float*  lxsm  = lysm + 14;                      // 14
    float*  vysm  = lxsm + 14;                      // 14
    float*  vxsm  = vysm + 14;                      // 14

    const int bid = blockIdx.x;
    const int k   = bid >> 1;
    const int h   = bid & 1;
    const int tid = threadIdx.x;
    const int b   = k >> 9;

    const float x1 = boxes[k * 4 + 0];
    const float y1 = boxes[k * 4 + 1];
    const float x2 = boxes[k * 4 + 2];
    const float y2 = boxes[k * 4 + 3];

    const float area = (x2 - x1) * (y2 - y1);
    const float sbox = sqrtf(fmaxf(area, 0.0f));
    const float lf   = floorf(4.0f + log2f(sbox / 224.0f) + 1e-6f);
    const int   lvl  = (int)fminf(fmaxf(lf, 2.0f), 5.0f) - 2;

    const int   H   = lvl == 0 ? 200 : lvl == 1 ? 100 : lvl == 2 ? 50 : 25;
    const float sc  = lvl == 0 ? 0.25f : lvl == 1 ? 0.125f : lvl == 2 ? 0.0625f : 0.03125f;
    const int   OFF = lvl == 0 ? 0 : lvl == 1 ? 20480000 : lvl == 2 ? 25600000 : 26880000;
    const int   W   = H;

    const float bx1 = x1 * sc, by1 = y1 * sc;
    const float bx2 = x2 * sc, by2 = y2 * sc;
    const float rw  = fmaxf(bx2 - bx1, 1.0f);
    const float rh  = fmaxf(by2 - by1, 1.0f);
    const float bw  = rw * (1.0f / 7.0f);
    const float bh  = rh * (1.0f / 7.0f);

    // --- phase 1: separable y / x sample precompute ---
    if (tid < 14) {
        const int iy = tid;
        const float y = by1 + (float)(iy >> 1) * bh + ((float)(iy & 1) + 0.5f) * bh * 0.5f;
        const float v = (y >= -1.0f && y <= (float)H) ? 1.0f : 0.0f;
        const float yc = fminf(fmaxf(y, 0.0f), (float)(H - 1));
        int yl = (int)floorf(yc);
        if (yl > H - 2) yl = H - 2;
        ylsm[iy] = yl;
        lysm[iy] = yc - (float)yl;
        vysm[iy] = v;
    } else if (tid >= 32 && tid < 46) {
        const int ix = tid - 32;
        const float x = bx1 + (float)(ix >> 1) * bw + ((float)(ix & 1) + 0.5f) * bw * 0.5f;
        const float v = (x >= -1.0f && x <= (float)W) ? 1.0f : 0.0f;
        const float xc = fminf(fmaxf(x, 0.0f), (float)(W - 1));
        int xl = (int)floorf(xc);
        if (xl > W - 2) xl = W - 2;
        xlsm[ix] = xl;
        lxsm[ix] = xc - (float)xl;
        vxsm[ix] = v;
    }
    __syncthreads();

    // --- phase 2: per-sample offset + 4 packed half2 weights (0.25 folded) ---
    for (int ss = tid; ss < NSAMP * NSAMP; ss += 256) {
        const int iy = ss / NSAMP;
        const int ix = ss - iy * NSAMP;
        const float ly = lysm[iy], lx = lxsm[ix];
        const float v  = vysm[iy] * vxsm[ix] * 0.25f;
        const float hy = 1.0f - ly, hx = 1.0f - lx;
        uint4 wq;
        wq.x = h2u(__float2half2_rn(hy * hx * v));
        wq.y = h2u(__float2half2_rn(hy * lx * v));
        wq.z = h2u(__float2half2_rn(ly * hx * v));
        wq.w = h2u(__float2half2_rn(ly * lx * v));
        whsm[ss]  = wq;
        offsm[ss] = (ylsm[iy] * W + xlsm[ix]) * NCH;   // in halves
    }
    __syncthreads();

    // --- phase 3: 49 bins over 16 bin-groups; HFMA2 taps, fp32 cross-sub ---
    const int cg = tid & 15;
    const int bg = tid >> 4;
    const __half* fb = g_cl + OFF + (size_t)b * H * W * NCH + h * 128 + cg * 8;
    const int rs = W * NCH;

    for (int bin = bg; bin < 49; bin += 16) {
        const int ph = bin / 7;
        const int pw = bin - ph * 7;
        float a0 = 0.f, a1 = 0.f, a2 = 0.f, a3 = 0.f;
        float a4 = 0.f, a5 = 0.f, a6 = 0.f, a7 = 0.f;
        #pragma unroll
        for (int sub = 0; sub < 4; ++sub) {
            const int sI = (ph * 2 + (sub >> 1)) * NSAMP + (pw * 2 + (sub & 1));
            const uint4 wq = whsm[sI];
            const int   o  = offsm[sI];
            const __half2 w00 = *(const __half2*)&wq.x;
            const __half2 w01 = *(const __half2*)&wq.y;
            const __half2 w10 = *(const __half2*)&wq.z;
            const __half2 w11 = *(const __half2*)&wq.w;
            const uint4 r00 = *(const uint4*)(fb + o);
            const uint4 r01 = *(const uint4*)(fb + o + NCH);
            const uint4 r10 = *(const uint4*)(fb + o + rs);
            const uint4 r11 = *(const uint4*)(fb + o + rs + NCH);
            #pragma unroll
            for (int j = 0; j < 4; ++j) {
                const __half2 v00 = ((const __half2*)&r00)[j];
                const __half2 v01 = ((const __half2*)&r01)[j];
                const __half2 v10 = ((const __half2*)&r10)[j];
                const __half2 v11 = ((const __half2*)&r11)[j];
                const __half2 t0 = __hfma2(w00, v00, __hmul2(w01, v01));
                const __half2 t1 = __hfma2(w10, v10, __hmul2(w11, v11));
                const float2 f0 = __half22float2(t0);
                const float2 f1 = __half22float2(t1);
                switch (j) {
                    case 0: a0 += f0.x + f1.x; a1 += f0.y + f1.y; break;
                    case 1: a2 += f0.x + f1.x; a3 += f0.y + f1.y; break;
                    case 2: a4 += f0.x + f1.x; a5 += f0.y + f1.y; break;
                    case 3: a6 += f0.x + f1.x; a7 += f0.y + f1.y; break;
                }
            }
        }
        const int base = (cg * 8) * 49 + bin;
        stage[base          ] = __float2half_rn(a0);
        stage[base +  49    ] = __float2half_rn(a1);
        stage[base +  49 * 2] = __float2half_rn(a2);
        stage[base +  49 * 3] = __float2half_rn(a3);
        stage[base +  49 * 4] = __float2half_rn(a4);
        stage[base +  49 * 5] = __float2half_rn(a5);
        stage[base +  49 * 6] = __float2half_rn(a6);
        stage[base +  49 * 7] = __float2half_rn(a7);
    }
    __syncthreads();

    // --- phase 4: coalesced writeback, fp16 stage -> f32 out (float4) ---
    float4* op = (float4*)(out + (size_t)k * OUT_PER_ROI + h * 6272);
    const uint2* sp = (const uint2*)stage;
    for (int v = tid; v < 6272 / 4; v += 256) {
        const uint2 r = sp[v];
        const float2 g0 = __half22float2(*(const __half2*)&r.x);
        const float2 g1 = __half22float2(*(const __half2*)&r.y);
        op[v] = make_float4(g0.x, g0.y, g1.x, g1.y);
    }
}

// ---------------------------------------------------------------------------
extern "C" void kernel_launch(void* const* d_in, const int* in_sizes, int n_in,
                              void* d_out, int out_size)
{
    (void)in_sizes; (void)n_in; (void)out_size;
    const float* boxes = (const float*)d_in[4];
    float* out = (float*)d_out;

    transpose_all<<<6656, 256>>>((const float*)d_in[0], (const float*)d_in[1],
                                 (const float*)d_in[2], (const float*)d_in[3]);

    roi_kernel<<<2 * K_ROIS, 256, SMEM_BYTES>>>(boxes, out);
}